// round 1
// baseline (speedup 1.0000x reference)
#include <cuda_runtime.h>
#include <cuda_bf16.h>
#include <mma.h>

using namespace nvcuda;

// ---------------- problem constants ----------------
#define BB   32
#define CC_  384
#define HH_  56
#define WW_  56
#define NS   3136        // H*W
#define MR   100352      // B*N  (divisible by 128)
#define HID  1536
#define NHEADS 8
#define HD   48
#define GG   7           // grid size
#define SSZ  8           // sparse size
#define NWIN 1568        // B*GG*GG
#define EPSV 1e-5f

// ---------------- scratch (device globals; allocation-free) ----------------
__device__ __align__(16) float          g_xT [(size_t)MR * CC_];       // [B,N,C] fp32
__device__ __align__(16) __nv_bfloat16  g_hln[(size_t)MR * CC_];       // LN1 out, window-major
__device__ __align__(16) __nv_bfloat16  g_qkv[(size_t)MR * 3 * CC_];   // window-major
__device__ __align__(16) __nv_bfloat16  g_o  [(size_t)MR * CC_];       // attn out, window-major
__device__ __align__(16) float          g_x1 [(size_t)MR * CC_];       // residual1, token-major
__device__ __align__(16) __nv_bfloat16  g_ln2[(size_t)MR * CC_];       // token-major
__device__ __align__(16) __nv_bfloat16  g_m1 [(size_t)MR * HID];       // fc1 out
__device__ __align__(16) __nv_bfloat16  g_mg [(size_t)MR * HID];       // dwconv+gelu out

// ---------------- K1: NCHW -> [B,N,C] transpose ----------------
__global__ void k_transpose(const float* __restrict__ x) {
    __shared__ float tile[32][33];
    int b  = blockIdx.z;
    int n0 = blockIdx.x * 32, c0 = blockIdx.y * 32;
    const float* in  = x    + (size_t)b * CC_ * NS;
    float*       out = g_xT + (size_t)b * NS * CC_;
    int tx = threadIdx.x, ty = threadIdx.y;  // (32,8)
#pragma unroll
    for (int i = 0; i < 32; i += 8)
        tile[ty + i][tx] = in[(size_t)(c0 + ty + i) * NS + n0 + tx];
    __syncthreads();
#pragma unroll
    for (int i = 0; i < 32; i += 8)
        out[(size_t)(n0 + ty + i) * CC_ + c0 + tx] = tile[tx][ty + i];
}

// ---------------- K2/K6: LayerNorm (MODE 0: LN1 + window gather, MODE 1: LN2) ----------------
template<int MODE>
__global__ void k_layernorm(const float* __restrict__ gam, const float* __restrict__ bet) {
    int r   = blockIdx.x;           // token-major row
    int tid = threadIdx.x;          // 128
    const float* src = (MODE == 0 ? g_xT : g_x1) + (size_t)r * CC_;
    float v0 = src[tid], v1 = src[tid + 128], v2 = src[tid + 256];
    float s  = v0 + v1 + v2;
    float sq = v0 * v0 + v1 * v1 + v2 * v2;
#pragma unroll
    for (int o = 16; o; o >>= 1) {
        s  += __shfl_xor_sync(0xffffffffu, s,  o);
        sq += __shfl_xor_sync(0xffffffffu, sq, o);
    }
    __shared__ float ws[4], wq[4];
    int w = tid >> 5, l = tid & 31;
    if (l == 0) { ws[w] = s; wq[w] = sq; }
    __syncthreads();
    float mean = (ws[0] + ws[1] + ws[2] + ws[3]) * (1.0f / CC_);
    float var  = (wq[0] + wq[1] + wq[2] + wq[3]) * (1.0f / CC_) - mean * mean;
    float rstd = rsqrtf(var + EPSV);

    size_t orow;
    if (MODE == 0) {
        int b = r / NS, n = r % NS;
        int h = n / WW_, wpos = n % WW_;
        int gi = h % GG,    si = h / GG;
        int gj = wpos % GG, sj = wpos / GG;
        int win = (b * GG + gi) * GG + gj;
        int t   = si * SSZ + sj;
        orow = (size_t)win * 64 + t;
    } else {
        orow = (size_t)r;
    }
    __nv_bfloat16* dst = (MODE == 0 ? g_hln : g_ln2) + orow * CC_;
    dst[tid]       = __float2bfloat16((v0 - mean) * rstd * gam[tid]       + bet[tid]);
    dst[tid + 128] = __float2bfloat16((v1 - mean) * rstd * gam[tid + 128] + bet[tid + 128]);
    dst[tid + 256] = __float2bfloat16((v2 - mean) * rstd * gam[tid + 256] + bet[tid + 256]);
}

// ---------------- generic 128x128 bf16 wmma GEMM with fused epilogues ----------------
// MODE 0: QKV   A=g_hln  K=384  N=1152 -> g_qkv (bf16)
// MODE 1: PROJ  A=g_o    K=384  N=384  -> g_x1 = xT + gamma1*(A@W + b)  (window->token scatter)
// MODE 2: FC1   A=g_ln2  K=384  N=1536 -> g_m1 = bf16(A@W + b)
// MODE 3: FC2   A=g_mg   K=1536 N=384  -> d_out[b,c,n] = x1 + gamma2*(A@W + b)  (NCHW permute)
template<int MODE>
__global__ void __launch_bounds__(256, 2) k_gemm(
    const float* __restrict__ Bw, const float* __restrict__ bias,
    const float* __restrict__ gamma, float* __restrict__ outp)
{
    constexpr int Kdim  = (MODE == 3) ? 1536 : 384;
    constexpr int Ncols = (MODE == 0) ? 1152 : ((MODE == 2) ? 1536 : 384);

    __shared__ __nv_bfloat16 sA[128 * 40];
    __shared__ __nv_bfloat16 sB[32 * 136];
    __shared__ float sEpi[8][16 * 20];

    const __nv_bfloat16* A =
        (MODE == 0) ? g_hln : (MODE == 1) ? g_o : (MODE == 2) ? g_ln2 : g_mg;

    int m0 = blockIdx.x * 128;
    int n0 = blockIdx.y * 128;
    int tid  = threadIdx.x;
    int warp = tid >> 5, lane = tid & 31;
    int wm = warp & 1, wn = warp >> 1;

    wmma::fragment<wmma::accumulator, 16, 16, 16, float> acc[4][2];
#pragma unroll
    for (int i = 0; i < 4; i++)
#pragma unroll
        for (int j = 0; j < 2; j++) wmma::fill_fragment(acc[i][j], 0.0f);

    int arow = tid >> 2;
    int akg  = (tid & 3) * 8;

    for (int k0 = 0; k0 < Kdim; k0 += 32) {
        *(uint4*)&sA[arow * 40 + akg] =
            *(const uint4*)&A[(size_t)(m0 + arow) * Kdim + k0 + akg];
        *(uint4*)&sA[(arow + 64) * 40 + akg] =
            *(const uint4*)&A[(size_t)(m0 + arow + 64) * Kdim + k0 + akg];
#pragma unroll
        for (int i = 0; i < 4; i++) {
            int linear = i * 1024 + tid * 4;
            int kr = linear >> 7, col = linear & 127;
            float4 f = *(const float4*)&Bw[(size_t)(k0 + kr) * Ncols + n0 + col];
            __nv_bfloat16* d = &sB[kr * 136 + col];
            d[0] = __float2bfloat16(f.x); d[1] = __float2bfloat16(f.y);
            d[2] = __float2bfloat16(f.z); d[3] = __float2bfloat16(f.w);
        }
        __syncthreads();
#pragma unroll
        for (int ks = 0; ks < 32; ks += 16) {
            wmma::fragment<wmma::matrix_a, 16, 16, 16, __nv_bfloat16, wmma::row_major> af[4];
            wmma::fragment<wmma::matrix_b, 16, 16, 16, __nv_bfloat16, wmma::row_major> bf[2];
#pragma unroll
            for (int i = 0; i < 4; i++)
                wmma::load_matrix_sync(af[i], &sA[(wm * 64 + i * 16) * 40 + ks], 40);
#pragma unroll
            for (int j = 0; j < 2; j++)
                wmma::load_matrix_sync(bf[j], &sB[ks * 136 + wn * 32 + j * 16], 136);
#pragma unroll
            for (int i = 0; i < 4; i++)
#pragma unroll
                for (int j = 0; j < 2; j++)
                    wmma::mma_sync(acc[i][j], af[i], bf[j], acc[i][j]);
        }
        __syncthreads();
    }

    // epilogue
#pragma unroll
    for (int i = 0; i < 4; i++) {
#pragma unroll
        for (int j = 0; j < 2; j++) {
            wmma::store_matrix_sync(&sEpi[warp][0], acc[i][j], 20, wmma::mem_row_major);
            __syncwarp();
            int growb = m0 + wm * 64 + i * 16;
            int gcolb = n0 + wn * 32 + j * 16;
#pragma unroll
            for (int e = 0; e < 8; e++) {
                int idx = e * 32 + lane;
                int rr, cc;
                if (MODE == 3) { cc = idx >> 4; rr = idx & 15; }     // column-major for coalesced n
                else           { rr = idx >> 4; cc = idx & 15; }
                float v = sEpi[warp][rr * 20 + cc];
                int grow = growb + rr, gcol = gcolb + cc;
                if (MODE == 0) {
                    g_qkv[(size_t)grow * Ncols + gcol] = __float2bfloat16(v);
                } else if (MODE == 2) {
                    g_m1[(size_t)grow * Ncols + gcol] = __float2bfloat16(v + bias[gcol]);
                } else if (MODE == 1) {
                    int win = grow >> 6, t = grow & 63;
                    int b = win / 49, wi = win % 49;
                    int gi = wi / 7, gj = wi % 7;
                    int si = t >> 3, sj = t & 7;
                    int h = si * GG + gi, wp = sj * GG + gj;
                    size_t ridx = ((size_t)b * NS + h * WW_ + wp) * CC_ + gcol;
                    g_x1[ridx] = g_xT[ridx] + gamma[gcol] * (v + bias[gcol]);
                } else {  // MODE 3
                    int b = grow / NS, n = grow % NS;
                    float ov = g_x1[(size_t)grow * CC_ + gcol]
                             + gamma[gcol] * (v + bias[gcol]);
                    outp[((size_t)b * CC_ + gcol) * NS + n] = ov;
                }
            }
            __syncwarp();
        }
    }
}

// ---------------- K4: attention, one block per (window, head), 4 warps ----------------
__global__ void __launch_bounds__(128) k_attn() {
    int win  = blockIdx.x;
    int head = blockIdx.y;
    __shared__ __nv_bfloat16 sq[64 * 56], sk[64 * 56], sv[64 * 56];
    __shared__ float sS[64 * 68];
    __shared__ __nv_bfloat16 sP[64 * 72];
    int tid = threadIdx.x;

    size_t base = (size_t)win * 64 * 1152;
#pragma unroll
    for (int m = 0; m < 3; m++) {
        const __nv_bfloat16* src = g_qkv + base + m * 384 + head * 48;
        __nv_bfloat16* dst = (m == 0) ? sq : (m == 1) ? sk : sv;
        for (int li = tid; li < 64 * 6; li += 128) {
            int t = li / 6, dg = (li % 6) * 8;
            *(uint4*)&dst[t * 56 + dg] = *(const uint4*)&src[(size_t)t * 1152 + dg];
        }
    }
    __syncthreads();

    int warp = tid >> 5;
    int m0 = warp * 16;
    {   // S = q @ k^T   [64x64], K=48
        wmma::fragment<wmma::accumulator, 16, 16, 16, float> acc[4];
#pragma unroll
        for (int j = 0; j < 4; j++) wmma::fill_fragment(acc[j], 0.0f);
#pragma unroll
        for (int k = 0; k < 48; k += 16) {
            wmma::fragment<wmma::matrix_a, 16, 16, 16, __nv_bfloat16, wmma::row_major> af;
            wmma::load_matrix_sync(af, &sq[m0 * 56 + k], 56);
#pragma unroll
            for (int j = 0; j < 4; j++) {
                wmma::fragment<wmma::matrix_b, 16, 16, 16, __nv_bfloat16, wmma::col_major> bf;
                wmma::load_matrix_sync(bf, &sk[(j * 16) * 56 + k], 56);
                wmma::mma_sync(acc[j], af, bf, acc[j]);
            }
        }
#pragma unroll
        for (int j = 0; j < 4; j++)
            wmma::store_matrix_sync(&sS[m0 * 68 + j * 16], acc[j], 68, wmma::mem_row_major);
    }
    __syncthreads();

    if (tid < 64) {  // softmax per row
        const float scale = 0.14433756729740643f;  // 48^-0.5
        float buf[64];
        float mx = -1e30f;
#pragma unroll
        for (int j = 0; j < 64; j++) { buf[j] = sS[tid * 68 + j] * scale; mx = fmaxf(mx, buf[j]); }
        float sum = 0.0f;
#pragma unroll
        for (int j = 0; j < 64; j++) { buf[j] = __expf(buf[j] - mx); sum += buf[j]; }
        float inv = 1.0f / sum;
#pragma unroll
        for (int j = 0; j < 64; j++) sP[tid * 72 + j] = __float2bfloat16(buf[j] * inv);
    }
    __syncthreads();

    {   // O = P @ V   [64x48], K=64
        wmma::fragment<wmma::accumulator, 16, 16, 16, float> acc[3];
#pragma unroll
        for (int j = 0; j < 3; j++) wmma::fill_fragment(acc[j], 0.0f);
#pragma unroll
        for (int k = 0; k < 64; k += 16) {
            wmma::fragment<wmma::matrix_a, 16, 16, 16, __nv_bfloat16, wmma::row_major> af;
            wmma::load_matrix_sync(af, &sP[m0 * 72 + k], 72);
#pragma unroll
            for (int j = 0; j < 3; j++) {
                wmma::fragment<wmma::matrix_b, 16, 16, 16, __nv_bfloat16, wmma::row_major> bf;
                wmma::load_matrix_sync(bf, &sv[k * 56 + j * 16], 56);
                wmma::mma_sync(acc[j], af, bf, acc[j]);
            }
        }
#pragma unroll
        for (int j = 0; j < 3; j++)
            wmma::store_matrix_sync(&sS[m0 * 68 + j * 16], acc[j], 68, wmma::mem_row_major);
    }
    __syncthreads();

    __nv_bfloat16* dst = g_o + (size_t)win * 64 * 384 + head * 48;
    for (int li = tid; li < 64 * 48; li += 128) {
        int t = li / 48, d = li % 48;
        dst[(size_t)t * 384 + d] = __float2bfloat16(sS[t * 68 + d]);
    }
}

// ---------------- K8: depthwise 3x3 conv + bias + exact GELU ----------------
__global__ void __launch_bounds__(256) k_dwconv(const float* __restrict__ wgt,
                                                const float* __restrict__ bias) {
    __shared__ __nv_bfloat16 s[3 * 58 * 64];
    int b = blockIdx.y, h = blockIdx.x;
    int tid = threadIdx.x;
    int c = tid & 63, wq = tid >> 6;  // c: channel-in-chunk, wq: 0..3

    for (int cc = 0; cc < HID; cc += 64) {
        __syncthreads();
        for (int li = tid; li < 3 * 58 * 8; li += 256) {
            int hr = li / 464;
            int rem = li % 464;
            int wi = rem >> 3;
            int grp = (rem & 7) * 8;
            int hh = h - 1 + hr, ww = wi - 1;
            uint4 val = make_uint4(0u, 0u, 0u, 0u);
            if (hh >= 0 && hh < HH_ && ww >= 0 && ww < WW_)
                val = *(const uint4*)&g_m1[((size_t)b * NS + hh * WW_ + ww) * HID + cc + grp];
            *(uint4*)&s[(hr * 58 + wi) * 64 + grp] = val;
        }
        __syncthreads();

        int ch = cc + c;
        float w9[9];
#pragma unroll
        for (int i = 0; i < 9; i++) w9[i] = wgt[ch * 9 + i];
        float bv = bias[ch];
        for (int p = 0; p < 14; p++) {
            int w0 = p * 4 + wq;
            float acc = bv;
#pragma unroll
            for (int dy = 0; dy < 3; dy++)
#pragma unroll
                for (int dx = 0; dx < 3; dx++)
                    acc += __bfloat162float(s[(dy * 58 + w0 + dx) * 64 + c]) * w9[dy * 3 + dx];
            float gl = 0.5f * acc * (1.0f + erff(acc * 0.70710678118f));
            g_mg[((size_t)b * NS + h * WW_ + w0) * HID + ch] = __float2bfloat16(gl);
        }
    }
}

// ---------------- launch ----------------
extern "C" void kernel_launch(void* const* d_in, const int* in_sizes, int n_in,
                              void* d_out, int out_size) {
    (void)in_sizes; (void)n_in; (void)out_size;
    const float* x      = (const float*)d_in[0];
    const float* ln1_g  = (const float*)d_in[1];
    const float* ln1_b  = (const float*)d_in[2];
    const float* qkv_w  = (const float*)d_in[3];
    const float* proj_w = (const float*)d_in[4];
    const float* proj_b = (const float*)d_in[5];
    const float* ln2_g  = (const float*)d_in[6];
    const float* ln2_b  = (const float*)d_in[7];
    const float* fc1_w  = (const float*)d_in[8];
    const float* fc1_b  = (const float*)d_in[9];
    const float* dw_w   = (const float*)d_in[10];
    const float* dw_b   = (const float*)d_in[11];
    const float* fc2_w  = (const float*)d_in[12];
    const float* fc2_b  = (const float*)d_in[13];
    const float* gamma1 = (const float*)d_in[14];
    const float* gamma2 = (const float*)d_in[15];
    float* out = (float*)d_out;

    k_transpose<<<dim3(NS / 32, CC_ / 32, BB), dim3(32, 8)>>>(x);
    k_layernorm<0><<<MR, 128>>>(ln1_g, ln1_b);
    k_gemm<0><<<dim3(MR / 128, 1152 / 128), 256>>>(qkv_w, nullptr, nullptr, nullptr);
    k_attn<<<dim3(NWIN, NHEADS), 128>>>();
    k_gemm<1><<<dim3(MR / 128, 384 / 128), 256>>>(proj_w, proj_b, gamma1, nullptr);
    k_layernorm<1><<<MR, 128>>>(ln2_g, ln2_b);
    k_gemm<2><<<dim3(MR / 128, 1536 / 128), 256>>>(fc1_w, fc1_b, nullptr, nullptr);
    k_dwconv<<<dim3(HH_, BB), 256>>>(dw_w, dw_b);
    k_gemm<3><<<dim3(MR / 128, 384 / 128), 256>>>(fc2_w, fc2_b, gamma2, out);
}

// round 5
// speedup vs baseline: 1.0751x; 1.0751x over previous
#include <cuda_runtime.h>
#include <cuda_bf16.h>
#include <mma.h>
#include <cstdint>

using namespace nvcuda;

// ---------------- problem constants ----------------
#define BB   32
#define CC_  384
#define HH_  56
#define WW_  56
#define NS   3136        // H*W
#define MR   100352      // B*N  (divisible by 128)
#define HID  1536
#define NHEADS 8
#define HD   48
#define GG   7           // grid size
#define SSZ  8           // sparse size
#define NWIN 1568        // B*GG*GG
#define EPSV 1e-5f

// ---------------- scratch (device globals; allocation-free) ----------------
__device__ __align__(16) float          g_xT [(size_t)MR * CC_];       // [B,N,C] fp32
__device__ __align__(16) __nv_bfloat16  g_hln[(size_t)MR * CC_];       // LN1 out, window-major
__device__ __align__(16) __nv_bfloat16  g_qkv[(size_t)MR * 3 * CC_];   // window-major
__device__ __align__(16) __nv_bfloat16  g_o  [(size_t)MR * CC_];       // attn out, window-major
__device__ __align__(16) float          g_x1 [(size_t)MR * CC_];       // residual1, token-major
__device__ __align__(16) __nv_bfloat16  g_ln2[(size_t)MR * CC_];       // token-major
__device__ __align__(16) __nv_bfloat16  g_m1 [(size_t)MR * HID];       // fc1 out
__device__ __align__(16) __nv_bfloat16  g_mg [(size_t)MR * HID];       // dwconv+gelu out
// bf16 weights, SAME [K, N] layout as the fp32 originals
__device__ __align__(16) __nv_bfloat16  g_wq[(size_t)384 * 1152];
__device__ __align__(16) __nv_bfloat16  g_wp[(size_t)384 * 384];
__device__ __align__(16) __nv_bfloat16  g_w1[(size_t)384 * 1536];
__device__ __align__(16) __nv_bfloat16  g_w2[(size_t)1536 * 384];

// ---------------- K0: weight fp32 -> bf16 convert (same layout) ----------------
template<int WID>
__global__ void k_wprep(const float* __restrict__ W) {
    constexpr size_t TOT = (WID == 0) ? (size_t)384 * 1152
                         : (WID == 1) ? (size_t)384 * 384
                         : (size_t)384 * 1536;   // WID 2 and 3 same element count
    __nv_bfloat16* Wt = (WID == 0) ? g_wq : (WID == 1) ? g_wp : (WID == 2) ? g_w1 : g_w2;
    size_t i = ((size_t)blockIdx.x * 256 + threadIdx.x) * 4;
    if (i < TOT) {
        float4 f = *(const float4*)&W[i];
        __nv_bfloat162 lo = __floats2bfloat162_rn(f.x, f.y);
        __nv_bfloat162 hi = __floats2bfloat162_rn(f.z, f.w);
        uint2 v = make_uint2(*(uint32_t*)&lo, *(uint32_t*)&hi);
        *(uint2*)&Wt[i] = v;
    }
}

// ---------------- K1: NCHW -> [B,N,C] transpose ----------------
__global__ void k_transpose(const float* __restrict__ x) {
    __shared__ float tile[32][33];
    int b  = blockIdx.z;
    int n0 = blockIdx.x * 32, c0 = blockIdx.y * 32;
    const float* in  = x    + (size_t)b * CC_ * NS;
    float*       out = g_xT + (size_t)b * NS * CC_;
    int tx = threadIdx.x, ty = threadIdx.y;  // (32,8)
#pragma unroll
    for (int i = 0; i < 32; i += 8)
        tile[ty + i][tx] = in[(size_t)(c0 + ty + i) * NS + n0 + tx];
    __syncthreads();
#pragma unroll
    for (int i = 0; i < 32; i += 8)
        out[(size_t)(n0 + ty + i) * CC_ + c0 + tx] = tile[tx][ty + i];
}

// ---------------- K2/K6: LayerNorm (MODE 0: LN1 + window gather, MODE 1: LN2) ----------------
template<int MODE>
__global__ void k_layernorm(const float* __restrict__ gam, const float* __restrict__ bet) {
    int r   = blockIdx.x;
    int tid = threadIdx.x;          // 128
    const float* src = (MODE == 0 ? g_xT : g_x1) + (size_t)r * CC_;
    float v0 = src[tid], v1 = src[tid + 128], v2 = src[tid + 256];
    float s  = v0 + v1 + v2;
    float sq = v0 * v0 + v1 * v1 + v2 * v2;
#pragma unroll
    for (int o = 16; o; o >>= 1) {
        s  += __shfl_xor_sync(0xffffffffu, s,  o);
        sq += __shfl_xor_sync(0xffffffffu, sq, o);
    }
    __shared__ float ws[4], wq[4];
    int w = tid >> 5, l = tid & 31;
    if (l == 0) { ws[w] = s; wq[w] = sq; }
    __syncthreads();
    float mean = (ws[0] + ws[1] + ws[2] + ws[3]) * (1.0f / CC_);
    float var  = (wq[0] + wq[1] + wq[2] + wq[3]) * (1.0f / CC_) - mean * mean;
    float rstd = rsqrtf(var + EPSV);

    size_t orow;
    if (MODE == 0) {
        int b = r / NS, n = r % NS;
        int h = n / WW_, wpos = n % WW_;
        int gi = h % GG,    si = h / GG;
        int gj = wpos % GG, sj = wpos / GG;
        int win = (b * GG + gi) * GG + gj;
        int t   = si * SSZ + sj;
        orow = (size_t)win * 64 + t;
    } else {
        orow = (size_t)r;
    }
    __nv_bfloat16* dst = (MODE == 0 ? g_hln : g_ln2) + orow * CC_;
    dst[tid]       = __float2bfloat16((v0 - mean) * rstd * gam[tid]       + bet[tid]);
    dst[tid + 128] = __float2bfloat16((v1 - mean) * rstd * gam[tid + 128] + bet[tid + 128]);
    dst[tid + 256] = __float2bfloat16((v2 - mean) * rstd * gam[tid + 256] + bet[tid + 256]);
}

// ---------------- wmma GEMM, 128x128 tile, K-tile 32, 2-stage cp.async ----------------
// 8 warps; warp (wm = w&3, wn = w>>2) computes rows [wm*32, wm*32+32) x cols [wn*64, wn*64+64).
// MODE 0: QKV   A=g_hln  K=384  N=1152 -> g_qkv (bf16)
// MODE 1: PROJ  A=g_o    K=384  N=384  -> g_x1 = xT + gamma1*(A@W + b)  (window->token scatter)
// MODE 2: FC1   A=g_ln2  K=384  N=1536 -> g_m1 = bf16(A@W + b)
// MODE 3: FC2   A=g_mg   K=1536 N=384  -> out[b,c,n] = x1 + gamma2*(A@W + b)  (NCHW permute)
template<int MODE>
__global__ void __launch_bounds__(256, 2) k_gemm(
    const float* __restrict__ bias, const float* __restrict__ gamma,
    float* __restrict__ outp)
{
    constexpr int Kdim  = (MODE == 3) ? 1536 : 384;
    constexpr int Ncols = (MODE == 0) ? 1152 : ((MODE == 2) ? 1536 : 384);
    constexpr int NKT   = Kdim / 32;

    const __nv_bfloat16* A  = (MODE == 0) ? g_hln : (MODE == 1) ? g_o : (MODE == 2) ? g_ln2 : g_mg;
    const __nv_bfloat16* Bw = (MODE == 0) ? g_wq  : (MODE == 1) ? g_wp : (MODE == 2) ? g_w1 : g_w2;

    __shared__ __align__(16) __nv_bfloat16 sA[2][128 * 40];   // row stride 40 elems (80 B)
    __shared__ __align__(16) __nv_bfloat16 sB[2][32 * 136];   // row stride 136 elems (272 B)
    __shared__ float sEpi[8][16 * 20];

    int n0 = blockIdx.x * 128;
    int m0 = blockIdx.y * 128;
    int tid  = threadIdx.x;
    int warp = tid >> 5, lane = tid & 31;
    int wm = warp & 3, wn = warp >> 2;

    wmma::fragment<wmma::accumulator, 16, 16, 16, float> acc[2][4];
#pragma unroll
    for (int i = 0; i < 2; i++)
#pragma unroll
        for (int j = 0; j < 4; j++) wmma::fill_fragment(acc[i][j], 0.0f);

    // cp.async stage loader: 1024 x 16B chunks (A 512, B 512), 4 per thread
    auto load_stage = [&](int kt, int buf) {
        int k0 = kt * 32;
#pragma unroll
        for (int s = 0; s < 4; s++) {
            int i = tid + s * 256;
            uint32_t dst; const __nv_bfloat16* src;
            if (i < 512) {           // A: 128 rows x 4 chunks (64 B/row)
                int r = i >> 2, c = i & 3;
                const __nv_bfloat16* sp = &sA[buf][r * 40 + c * 8];
                uint32_t a; asm("{ .reg .u64 t; cvta.to.shared.u64 t, %1; cvt.u32.u64 %0, t; }" : "=r"(a) : "l"(sp));
                dst = a;
                src = A + (size_t)(m0 + r) * Kdim + k0 + c * 8;
            } else {                 // B: 32 rows x 16 chunks (256 B/row)
                int j = i - 512, r = j >> 4, c = j & 15;
                const __nv_bfloat16* sp = &sB[buf][r * 136 + c * 8];
                uint32_t a; asm("{ .reg .u64 t; cvta.to.shared.u64 t, %1; cvt.u32.u64 %0, t; }" : "=r"(a) : "l"(sp));
                dst = a;
                src = Bw + (size_t)(k0 + r) * Ncols + n0 + c * 8;
            }
            asm volatile("cp.async.cg.shared.global [%0], [%1], 16;" :: "r"(dst), "l"(src));
        }
        asm volatile("cp.async.commit_group;" ::: "memory");
    };

    load_stage(0, 0);

    for (int kt = 0; kt < NKT; ++kt) {
        int buf = kt & 1;
        if (kt + 1 < NKT) {
            load_stage(kt + 1, buf ^ 1);
            asm volatile("cp.async.wait_group 1;" ::: "memory");
        } else {
            asm volatile("cp.async.wait_group 0;" ::: "memory");
        }
        __syncthreads();
#pragma unroll
        for (int ks = 0; ks < 32; ks += 16) {
            wmma::fragment<wmma::matrix_a, 16, 16, 16, __nv_bfloat16, wmma::row_major> af[2];
            wmma::fragment<wmma::matrix_b, 16, 16, 16, __nv_bfloat16, wmma::row_major> bf[4];
#pragma unroll
            for (int i = 0; i < 2; i++)
                wmma::load_matrix_sync(af[i], &sA[buf][(wm * 32 + i * 16) * 40 + ks], 40);
#pragma unroll
            for (int j = 0; j < 4; j++)
                wmma::load_matrix_sync(bf[j], &sB[buf][ks * 136 + wn * 64 + j * 16], 136);
#pragma unroll
            for (int i = 0; i < 2; i++)
#pragma unroll
                for (int j = 0; j < 4; j++)
                    wmma::mma_sync(acc[i][j], af[i], bf[j], acc[i][j]);
        }
        __syncthreads();
    }

    // ---------------- epilogue (per-warp staging through sEpi) ----------------
#pragma unroll
    for (int i = 0; i < 2; i++) {
#pragma unroll
        for (int j = 0; j < 4; j++) {
            wmma::store_matrix_sync(&sEpi[warp][0], acc[i][j], 20, wmma::mem_row_major);
            __syncwarp();
            int growb = m0 + wm * 32 + i * 16;
            int gcolb = n0 + wn * 64 + j * 16;
#pragma unroll
            for (int e = 0; e < 8; e++) {
                int idx = e * 32 + lane;
                int rr, cc;
                if (MODE == 3) { cc = idx >> 4; rr = idx & 15; }     // column-major: coalesced over n
                else           { rr = idx >> 4; cc = idx & 15; }
                float v = sEpi[warp][rr * 20 + cc];
                int grow = growb + rr, gcol = gcolb + cc;
                if (MODE == 0) {
                    g_qkv[(size_t)grow * Ncols + gcol] = __float2bfloat16(v);
                } else if (MODE == 2) {
                    g_m1[(size_t)grow * Ncols + gcol] = __float2bfloat16(v + bias[gcol]);
                } else if (MODE == 1) {
                    int win = grow >> 6, t = grow & 63;
                    int b = win / 49, wi = win % 49;
                    int gi = wi / 7, gj = wi % 7;
                    int si = t >> 3, sj = t & 7;
                    int h = si * GG + gi, wp = sj * GG + gj;
                    size_t ridx = ((size_t)b * NS + h * WW_ + wp) * CC_ + gcol;
                    g_x1[ridx] = g_xT[ridx] + gamma[gcol] * (v + bias[gcol]);
                } else {  // MODE 3
                    int b = grow / NS, n = grow % NS;
                    float ov = g_x1[(size_t)grow * CC_ + gcol]
                             + gamma[gcol] * (v + bias[gcol]);
                    outp[((size_t)b * CC_ + gcol) * NS + n] = ov;
                }
            }
            __syncwarp();
        }
    }
}

// ---------------- K4: attention, one block per (window, head), 4 warps ----------------
__global__ void __launch_bounds__(128) k_attn() {
    int win  = blockIdx.x;
    int head = blockIdx.y;
    __shared__ __nv_bfloat16 sq[64 * 56], sk[64 * 56], sv[64 * 56];
    __shared__ float sS[64 * 68];
    __shared__ __nv_bfloat16 sP[64 * 72];
    int tid = threadIdx.x;

    size_t base = (size_t)win * 64 * 1152;
#pragma unroll
    for (int m = 0; m < 3; m++) {
        const __nv_bfloat16* src = g_qkv + base + m * 384 + head * 48;
        __nv_bfloat16* dst = (m == 0) ? sq : (m == 1) ? sk : sv;
        for (int li = tid; li < 64 * 6; li += 128) {
            int t = li / 6, dg = (li % 6) * 8;
            *(uint4*)&dst[t * 56 + dg] = *(const uint4*)&src[(size_t)t * 1152 + dg];
        }
    }
    __syncthreads();

    int warp = tid >> 5;
    int m0 = warp * 16;
    {   // S = q @ k^T   [64x64], K=48
        wmma::fragment<wmma::accumulator, 16, 16, 16, float> acc[4];
#pragma unroll
        for (int j = 0; j < 4; j++) wmma::fill_fragment(acc[j], 0.0f);
#pragma unroll
        for (int k = 0; k < 48; k += 16) {
            wmma::fragment<wmma::matrix_a, 16, 16, 16, __nv_bfloat16, wmma::row_major> af;
            wmma::load_matrix_sync(af, &sq[m0 * 56 + k], 56);
#pragma unroll
            for (int j = 0; j < 4; j++) {
                wmma::fragment<wmma::matrix_b, 16, 16, 16, __nv_bfloat16, wmma::col_major> bf;
                wmma::load_matrix_sync(bf, &sk[(j * 16) * 56 + k], 56);
                wmma::mma_sync(acc[j], af, bf, acc[j]);
            }
        }
#pragma unroll
        for (int j = 0; j < 4; j++)
            wmma::store_matrix_sync(&sS[m0 * 68 + j * 16], acc[j], 68, wmma::mem_row_major);
    }
    __syncthreads();

    if (tid < 64) {  // softmax per row
        const float scale = 0.14433756729740643f;  // 48^-0.5
        float buf[64];
        float mx = -1e30f;
#pragma unroll
        for (int j = 0; j < 64; j++) { buf[j] = sS[tid * 68 + j] * scale; mx = fmaxf(mx, buf[j]); }
        float sum = 0.0f;
#pragma unroll
        for (int j = 0; j < 64; j++) { buf[j] = __expf(buf[j] - mx); sum += buf[j]; }
        float inv = 1.0f / sum;
#pragma unroll
        for (int j = 0; j < 64; j++) sP[tid * 72 + j] = __float2bfloat16(buf[j] * inv);
    }
    __syncthreads();

    {   // O = P @ V   [64x48], K=64
        wmma::fragment<wmma::accumulator, 16, 16, 16, float> acc[3];
#pragma unroll
        for (int j = 0; j < 3; j++) wmma::fill_fragment(acc[j], 0.0f);
#pragma unroll
        for (int k = 0; k < 64; k += 16) {
            wmma::fragment<wmma::matrix_a, 16, 16, 16, __nv_bfloat16, wmma::row_major> af;
            wmma::load_matrix_sync(af, &sP[m0 * 72 + k], 72);
#pragma unroll
            for (int j = 0; j < 3; j++) {
                wmma::fragment<wmma::matrix_b, 16, 16, 16, __nv_bfloat16, wmma::row_major> bf;
                wmma::load_matrix_sync(bf, &sv[k * 56 + j * 16], 56);
                wmma::mma_sync(acc[j], af, bf, acc[j]);
            }
        }
#pragma unroll
        for (int j = 0; j < 3; j++)
            wmma::store_matrix_sync(&sS[m0 * 68 + j * 16], acc[j], 68, wmma::mem_row_major);
    }
    __syncthreads();

    __nv_bfloat16* dst = g_o + (size_t)win * 64 * 384 + head * 48;
    for (int li = tid; li < 64 * 48; li += 128) {
        int t = li / 48, d = li % 48;
        dst[(size_t)t * 384 + d] = __float2bfloat16(sS[t * 68 + d]);
    }
}

// ---------------- K8: depthwise 3x3 conv + bias + exact GELU ----------------
__global__ void __launch_bounds__(256) k_dwconv(const float* __restrict__ wgt,
                                                const float* __restrict__ bias) {
    __shared__ __nv_bfloat16 s[3 * 58 * 64];
    int b = blockIdx.y, h = blockIdx.x;
    int tid = threadIdx.x;
    int c = tid & 63, wq = tid >> 6;

    for (int cc = 0; cc < HID; cc += 64) {
        __syncthreads();
        for (int li = tid; li < 3 * 58 * 8; li += 256) {
            int hr = li / 464;
            int rem = li % 464;
            int wi = rem >> 3;
            int grp = (rem & 7) * 8;
            int hh = h - 1 + hr, ww = wi - 1;
            uint4 val = make_uint4(0u, 0u, 0u, 0u);
            if (hh >= 0 && hh < HH_ && ww >= 0 && ww < WW_)
                val = *(const uint4*)&g_m1[((size_t)b * NS + hh * WW_ + ww) * HID + cc + grp];
            *(uint4*)&s[(hr * 58 + wi) * 64 + grp] = val;
        }
        __syncthreads();

        int ch = cc + c;
        float w9[9];
#pragma unroll
        for (int i = 0; i < 9; i++) w9[i] = wgt[ch * 9 + i];
        float bv = bias[ch];
        for (int p = 0; p < 14; p++) {
            int w0 = p * 4 + wq;
            float acc = bv;
#pragma unroll
            for (int dy = 0; dy < 3; dy++)
#pragma unroll
                for (int dx = 0; dx < 3; dx++)
                    acc += __bfloat162float(s[(dy * 58 + w0 + dx) * 64 + c]) * w9[dy * 3 + dx];
            float gl = 0.5f * acc * (1.0f + erff(acc * 0.70710678118f));
            g_mg[((size_t)b * NS + h * WW_ + w0) * HID + ch] = __float2bfloat16(gl);
        }
    }
}

// ---------------- launch ----------------
extern "C" void kernel_launch(void* const* d_in, const int* in_sizes, int n_in,
                              void* d_out, int out_size) {
    (void)in_sizes; (void)n_in; (void)out_size;
    const float* x      = (const float*)d_in[0];
    const float* ln1_g  = (const float*)d_in[1];
    const float* ln1_b  = (const float*)d_in[2];
    const float* qkv_w  = (const float*)d_in[3];
    const float* proj_w = (const float*)d_in[4];
    const float* proj_b = (const float*)d_in[5];
    const float* ln2_g  = (const float*)d_in[6];
    const float* ln2_b  = (const float*)d_in[7];
    const float* fc1_w  = (const float*)d_in[8];
    const float* fc1_b  = (const float*)d_in[9];
    const float* dw_w   = (const float*)d_in[10];
    const float* dw_b   = (const float*)d_in[11];
    const float* fc2_w  = (const float*)d_in[12];
    const float* fc2_b  = (const float*)d_in[13];
    const float* gamma1 = (const float*)d_in[14];
    const float* gamma2 = (const float*)d_in[15];
    float* out = (float*)d_out;

    k_wprep<0><<<432, 256>>>(qkv_w);   // 384*1152 / 4 / 256
    k_wprep<1><<<144, 256>>>(proj_w);  // 384*384
    k_wprep<2><<<576, 256>>>(fc1_w);   // 384*1536
    k_wprep<3><<<576, 256>>>(fc2_w);   // 1536*384

    k_transpose<<<dim3(NS / 32, CC_ / 32, BB), dim3(32, 8)>>>(x);
    k_layernorm<0><<<MR, 128>>>(ln1_g, ln1_b);
    k_gemm<0><<<dim3(1152 / 128, MR / 128), 256>>>(nullptr, nullptr, nullptr);
    k_attn<<<dim3(NWIN, NHEADS), 128>>>();
    k_gemm<1><<<dim3(384 / 128, MR / 128), 256>>>(proj_b, gamma1, nullptr);
    k_layernorm<1><<<MR, 128>>>(ln2_g, ln2_b);
    k_gemm<2><<<dim3(1536 / 128, MR / 128), 256>>>(fc1_b, nullptr, nullptr);
    k_dwconv<<<dim3(HH_, BB), 256>>>(dw_w, dw_b);
    k_gemm<3><<<dim3(384 / 128, MR / 128), 256>>>(fc2_b, gamma2, out);
}

// round 9
// speedup vs baseline: 1.1040x; 1.0269x over previous
#include <cuda_runtime.h>
#include <cuda_bf16.h>
#include <mma.h>
#include <cstdint>

using namespace nvcuda;

// ---------------- problem constants ----------------
#define BB   32
#define CC_  384
#define HH_  56
#define WW_  56
#define NS   3136        // H*W
#define MR   100352      // B*N  (divisible by 128)
#define HID  1536
#define NHEADS 8
#define HD   48
#define GG   7           // grid size
#define SSZ  8           // sparse size
#define NWIN 1568        // B*GG*GG
#define EPSV 1e-5f

// ---------------- scratch (device globals; allocation-free) ----------------
__device__ __align__(16) float          g_xT [(size_t)MR * CC_];       // [B,N,C] fp32
__device__ __align__(16) __nv_bfloat16  g_hln[(size_t)MR * CC_];       // LN1 out, window-major
__device__ __align__(16) __nv_bfloat16  g_qkv[(size_t)MR * 3 * CC_];   // window-major
__device__ __align__(16) __nv_bfloat16  g_o  [(size_t)MR * CC_];       // attn out, window-major
__device__ __align__(16) float          g_x1 [(size_t)MR * CC_];       // residual1, token-major
__device__ __align__(16) __nv_bfloat16  g_ln2[(size_t)MR * CC_];       // token-major
__device__ __align__(16) __nv_bfloat16  g_m1 [(size_t)MR * HID];       // fc1 out
__device__ __align__(16) __nv_bfloat16  g_mg [(size_t)MR * HID];       // dwconv+gelu out
// bf16 weights, SAME [K, N] layout as the fp32 originals
__device__ __align__(16) __nv_bfloat16  g_wq[(size_t)384 * 1152];
__device__ __align__(16) __nv_bfloat16  g_wp[(size_t)384 * 384];
__device__ __align__(16) __nv_bfloat16  g_w1[(size_t)384 * 1536];
__device__ __align__(16) __nv_bfloat16  g_w2[(size_t)1536 * 384];

// ---------------- K0: ALL weight fp32 -> bf16 converts in ONE kernel ----------------
// segments (elems): qkv 442368 | proj 147456 | fc1 589824 | fc2 589824  (total 1769472)
__global__ void k_wprep_all(const float* __restrict__ qkv_w, const float* __restrict__ proj_w,
                            const float* __restrict__ fc1_w, const float* __restrict__ fc2_w) {
    size_t i = ((size_t)blockIdx.x * 256 + threadIdx.x) * 4;
    const float* src; __nv_bfloat16* dst; size_t off;
    if (i < 442368)        { src = qkv_w;  dst = g_wq; off = i; }
    else if (i < 589824)   { src = proj_w; dst = g_wp; off = i - 442368; }
    else if (i < 1179648)  { src = fc1_w;  dst = g_w1; off = i - 589824; }
    else if (i < 1769472)  { src = fc2_w;  dst = g_w2; off = i - 1179648; }
    else return;
    float4 f = *(const float4*)&src[off];
    __nv_bfloat162 lo = __floats2bfloat162_rn(f.x, f.y);
    __nv_bfloat162 hi = __floats2bfloat162_rn(f.z, f.w);
    *(uint2*)&dst[off] = make_uint2(*(uint32_t*)&lo, *(uint32_t*)&hi);
}

// ---------------- K1: NCHW -> [B,N,C] transpose ----------------
__global__ void k_transpose(const float* __restrict__ x) {
    __shared__ float tile[32][33];
    int b  = blockIdx.z;
    int n0 = blockIdx.x * 32, c0 = blockIdx.y * 32;
    const float* in  = x    + (size_t)b * CC_ * NS;
    float*       out = g_xT + (size_t)b * NS * CC_;
    int tx = threadIdx.x, ty = threadIdx.y;  // (32,8)
#pragma unroll
    for (int i = 0; i < 32; i += 8)
        tile[ty + i][tx] = in[(size_t)(c0 + ty + i) * NS + n0 + tx];
    __syncthreads();
#pragma unroll
    for (int i = 0; i < 32; i += 8)
        out[(size_t)(n0 + ty + i) * CC_ + c0 + tx] = tile[tx][ty + i];
}

// ---------------- K2/K6: LayerNorm (MODE 0: LN1 + window gather, MODE 1: LN2) ----------------
template<int MODE>
__global__ void k_layernorm(const float* __restrict__ gam, const float* __restrict__ bet) {
    int r   = blockIdx.x;
    int tid = threadIdx.x;          // 128
    const float* src = (MODE == 0 ? g_xT : g_x1) + (size_t)r * CC_;
    float v0 = src[tid], v1 = src[tid + 128], v2 = src[tid + 256];
    float s  = v0 + v1 + v2;
    float sq = v0 * v0 + v1 * v1 + v2 * v2;
#pragma unroll
    for (int o = 16; o; o >>= 1) {
        s  += __shfl_xor_sync(0xffffffffu, s,  o);
        sq += __shfl_xor_sync(0xffffffffu, sq, o);
    }
    __shared__ float ws[4], wq[4];
    int w = tid >> 5, l = tid & 31;
    if (l == 0) { ws[w] = s; wq[w] = sq; }
    __syncthreads();
    float mean = (ws[0] + ws[1] + ws[2] + ws[3]) * (1.0f / CC_);
    float var  = (wq[0] + wq[1] + wq[2] + wq[3]) * (1.0f / CC_) - mean * mean;
    float rstd = rsqrtf(var + EPSV);

    size_t orow;
    if (MODE == 0) {
        int b = r / NS, n = r % NS;
        int h = n / WW_, wpos = n % WW_;
        int gi = h % GG,    si = h / GG;
        int gj = wpos % GG, sj = wpos / GG;
        int win = (b * GG + gi) * GG + gj;
        int t   = si * SSZ + sj;
        orow = (size_t)win * 64 + t;
    } else {
        orow = (size_t)r;
    }
    __nv_bfloat16* dst = (MODE == 0 ? g_hln : g_ln2) + orow * CC_;
    dst[tid]       = __float2bfloat16((v0 - mean) * rstd * gam[tid]       + bet[tid]);
    dst[tid + 128] = __float2bfloat16((v1 - mean) * rstd * gam[tid + 128] + bet[tid + 128]);
    dst[tid + 256] = __float2bfloat16((v2 - mean) * rstd * gam[tid + 256] + bet[tid + 256]);
}

// ---------------- wmma GEMM, 128x128 tile, K-tile 32, 3-stage cp.async ----------------
// dynamic smem: 3 stages x (A 10240 B + B 8704 B) = 56832 B; epilogue staging aliases stage 0.
// One __syncthreads per K-iter: buffer (kt+2)%3 was last read at compute kt-1, and every
// warp passed the top-of-iter barrier after compute kt-1, so the load is race-free.
// MODE 0: QKV   A=g_hln  K=384  N=1152 -> g_qkv (bf16)
// MODE 1: PROJ  A=g_o    K=384  N=384  -> g_x1 = xT + gamma1*(A@W + b)  (window->token scatter)
// MODE 2: FC1   A=g_ln2  K=384  N=1536 -> g_m1 = bf16(A@W + b)
// MODE 3: FC2   A=g_mg   K=1536 N=384  -> out[b,c,n] = x1 + gamma2*(A@W + b)  (NCHW permute)
#define STG_BYTES 18944
#define GEMM_DSMEM (3 * STG_BYTES)

__device__ __forceinline__ uint32_t sptr(const void* p) {
    uint32_t a;
    asm("{ .reg .u64 t; cvta.to.shared.u64 t, %1; cvt.u32.u64 %0, t; }" : "=r"(a) : "l"(p));
    return a;
}

template<int MODE>
__global__ void __launch_bounds__(256, 2) k_gemm(
    const float* __restrict__ bias, const float* __restrict__ gamma,
    float* __restrict__ outp)
{
    constexpr int Kdim  = (MODE == 3) ? 1536 : 384;
    constexpr int Ncols = (MODE == 0) ? 1152 : ((MODE == 2) ? 1536 : 384);
    constexpr int NKT   = Kdim / 32;

    const __nv_bfloat16* A  = (MODE == 0) ? g_hln : (MODE == 1) ? g_o : (MODE == 2) ? g_ln2 : g_mg;
    const __nv_bfloat16* Bw = (MODE == 0) ? g_wq  : (MODE == 1) ? g_wp : (MODE == 2) ? g_w1 : g_w2;

    extern __shared__ __align__(16) char dsm[];

    int n0 = blockIdx.x * 128;
    int m0 = blockIdx.y * 128;
    int tid  = threadIdx.x;
    int warp = tid >> 5, lane = tid & 31;
    int wm = warp & 3, wn = warp >> 2;   // warp tile: rows [wm*32,+32), cols [wn*64,+64)

    wmma::fragment<wmma::accumulator, 16, 16, 16, float> acc[2][4];
#pragma unroll
    for (int i = 0; i < 2; i++)
#pragma unroll
        for (int j = 0; j < 4; j++) wmma::fill_fragment(acc[i][j], 0.0f);

    // stage s: A at dsm + s*STG (128 rows x 40 elems), B at +10240 (32 rows x 136 elems)
    auto load_stage = [&](int kt, int buf) {
        int k0 = kt * 32;
        char* st = dsm + buf * STG_BYTES;
#pragma unroll
        for (int s = 0; s < 4; s++) {
            int i = tid + s * 256;
            uint32_t dst; const __nv_bfloat16* src;
            if (i < 512) {           // A: 128 rows x 4 chunks of 16B
                int r = i >> 2, c = i & 3;
                dst = sptr(st + (r * 40 + c * 8) * 2);
                src = A + (size_t)(m0 + r) * Kdim + k0 + c * 8;
            } else {                 // B: 32 rows x 16 chunks of 16B
                int j = i - 512, r = j >> 4, c = j & 15;
                dst = sptr(st + 10240 + (r * 136 + c * 8) * 2);
                src = Bw + (size_t)(k0 + r) * Ncols + n0 + c * 8;
            }
            asm volatile("cp.async.cg.shared.global [%0], [%1], 16;" :: "r"(dst), "l"(src));
        }
        asm volatile("cp.async.commit_group;" ::: "memory");
    };

    load_stage(0, 0);
    load_stage(1, 1);

    for (int kt = 0; kt < NKT; ++kt) {
        asm volatile("cp.async.wait_group 1;" ::: "memory");   // group kt complete
        __syncthreads();                                       // data visible; frees buf (kt+2)%3
        int nb = kt + 2;
        if (nb < NKT) load_stage(nb, nb % 3);
        else asm volatile("cp.async.commit_group;" ::: "memory");  // uniform group count

        const __nv_bfloat16* cA = (const __nv_bfloat16*)(dsm + (kt % 3) * STG_BYTES);
        const __nv_bfloat16* cB = (const __nv_bfloat16*)(dsm + (kt % 3) * STG_BYTES + 10240);
#pragma unroll
        for (int ks = 0; ks < 32; ks += 16) {
            wmma::fragment<wmma::matrix_a, 16, 16, 16, __nv_bfloat16, wmma::row_major> af[2];
            wmma::fragment<wmma::matrix_b, 16, 16, 16, __nv_bfloat16, wmma::row_major> bf[4];
#pragma unroll
            for (int i = 0; i < 2; i++)
                wmma::load_matrix_sync(af[i], &cA[(wm * 32 + i * 16) * 40 + ks], 40);
#pragma unroll
            for (int j = 0; j < 4; j++)
                wmma::load_matrix_sync(bf[j], &cB[ks * 136 + wn * 64 + j * 16], 136);
#pragma unroll
            for (int i = 0; i < 2; i++)
#pragma unroll
                for (int j = 0; j < 4; j++)
                    wmma::mma_sync(acc[i][j], af[i], bf[j], acc[i][j]);
        }
    }
    __syncthreads();   // all compute done before aliasing stage smem for epilogue

    float* sEpi = (float*)dsm + warp * 320;   // 8 warps x 16x20 floats = 10240 B (fits stage 0)

#pragma unroll
    for (int i = 0; i < 2; i++) {
#pragma unroll
        for (int j = 0; j < 4; j++) {
            wmma::store_matrix_sync(sEpi, acc[i][j], 20, wmma::mem_row_major);
            __syncwarp();
            int growb = m0 + wm * 32 + i * 16;
            int gcolb = n0 + wn * 64 + j * 16;
#pragma unroll
            for (int e = 0; e < 8; e++) {
                int idx = e * 32 + lane;
                int rr, cc;
                if (MODE == 3) { cc = idx >> 4; rr = idx & 15; }     // column-major: coalesced over n
                else           { rr = idx >> 4; cc = idx & 15; }
                float v = sEpi[rr * 20 + cc];
                int grow = growb + rr, gcol = gcolb + cc;
                if (MODE == 0) {
                    g_qkv[(size_t)grow * Ncols + gcol] = __float2bfloat16(v);
                } else if (MODE == 2) {
                    g_m1[(size_t)grow * Ncols + gcol] = __float2bfloat16(v + bias[gcol]);
                } else if (MODE == 1) {
                    int win = grow >> 6, t = grow & 63;
                    int b = win / 49, wi = win % 49;
                    int gi = wi / 7, gj = wi % 7;
                    int si = t >> 3, sj = t & 7;
                    int h = si * GG + gi, wp = sj * GG + gj;
                    size_t ridx = ((size_t)b * NS + h * WW_ + wp) * CC_ + gcol;
                    g_x1[ridx] = g_xT[ridx] + gamma[gcol] * (v + bias[gcol]);
                } else {  // MODE 3
                    int b = grow / NS, n = grow % NS;
                    float ov = g_x1[(size_t)grow * CC_ + gcol]
                             + gamma[gcol] * (v + bias[gcol]);
                    outp[((size_t)b * CC_ + gcol) * NS + n] = ov;
                }
            }
            __syncwarp();
        }
    }
}

// ---------------- K4: attention, one block per (window, head), 4 warps ----------------
__global__ void __launch_bounds__(128) k_attn() {
    int win  = blockIdx.x;
    int head = blockIdx.y;
    __shared__ __nv_bfloat16 sq[64 * 56], sk[64 * 56], sv[64 * 56];
    __shared__ float sS[64 * 68];
    __shared__ __nv_bfloat16 sP[64 * 72];
    __shared__ float red[128];
    int tid = threadIdx.x;

    size_t base = (size_t)win * 64 * 1152;
#pragma unroll
    for (int m = 0; m < 3; m++) {
        const __nv_bfloat16* src = g_qkv + base + m * 384 + head * 48;
        __nv_bfloat16* dst = (m == 0) ? sq : (m == 1) ? sk : sv;
        for (int li = tid; li < 64 * 6; li += 128) {
            int t = li / 6, dg = (li % 6) * 8;
            *(uint4*)&dst[t * 56 + dg] = *(const uint4*)&src[(size_t)t * 1152 + dg];
        }
    }
    __syncthreads();

    int warp = tid >> 5;
    int m0 = warp * 16;
    {   // S = q @ k^T   [64x64], K=48
        wmma::fragment<wmma::accumulator, 16, 16, 16, float> acc[4];
#pragma unroll
        for (int j = 0; j < 4; j++) wmma::fill_fragment(acc[j], 0.0f);
#pragma unroll
        for (int k = 0; k < 48; k += 16) {
            wmma::fragment<wmma::matrix_a, 16, 16, 16, __nv_bfloat16, wmma::row_major> af;
            wmma::load_matrix_sync(af, &sq[m0 * 56 + k], 56);
#pragma unroll
            for (int j = 0; j < 4; j++) {
                wmma::fragment<wmma::matrix_b, 16, 16, 16, __nv_bfloat16, wmma::col_major> bf;
                wmma::load_matrix_sync(bf, &sk[(j * 16) * 56 + k], 56);
                wmma::mma_sync(acc[j], af, bf, acc[j]);
            }
        }
#pragma unroll
        for (int j = 0; j < 4; j++)
            wmma::store_matrix_sync(&sS[m0 * 68 + j * 16], acc[j], 68, wmma::mem_row_major);
    }
    __syncthreads();

    {   // softmax: 128 threads, 2 per row (each handles 32 cols), smem combine
        const float scale = 0.14433756729740643f;  // 48^-0.5
        int row = tid & 63, half = tid >> 6;
        const float* Srow = &sS[row * 68 + half * 32];
        float buf[32];
        float mx = -1e30f;
#pragma unroll
        for (int j = 0; j < 32; j++) { buf[j] = Srow[j] * scale; mx = fmaxf(mx, buf[j]); }
        red[tid] = mx;
        __syncthreads();
        mx = fmaxf(red[row], red[row + 64]);
        float sum = 0.0f;
#pragma unroll
        for (int j = 0; j < 32; j++) { buf[j] = __expf(buf[j] - mx); sum += buf[j]; }
        __syncthreads();
        red[tid] = sum;
        __syncthreads();
        float inv = 1.0f / (red[row] + red[row + 64]);
        __nv_bfloat16* Prow = &sP[row * 72 + half * 32];
#pragma unroll
        for (int j = 0; j < 32; j++) Prow[j] = __float2bfloat16(buf[j] * inv);
    }
    __syncthreads();

    {   // O = P @ V   [64x48], K=64
        wmma::fragment<wmma::accumulator, 16, 16, 16, float> acc[3];
#pragma unroll
        for (int j = 0; j < 3; j++) wmma::fill_fragment(acc[j], 0.0f);
#pragma unroll
        for (int k = 0; k < 64; k += 16) {
            wmma::fragment<wmma::matrix_a, 16, 16, 16, __nv_bfloat16, wmma::row_major> af;
            wmma::load_matrix_sync(af, &sP[m0 * 72 + k], 72);
#pragma unroll
            for (int j = 0; j < 3; j++) {
                wmma::fragment<wmma::matrix_b, 16, 16, 16, __nv_bfloat16, wmma::row_major> bf;
                wmma::load_matrix_sync(bf, &sv[k * 56 + j * 16], 56);
                wmma::mma_sync(acc[j], af, bf, acc[j]);
            }
        }
#pragma unroll
        for (int j = 0; j < 3; j++)
            wmma::store_matrix_sync(&sS[m0 * 68 + j * 16], acc[j], 68, wmma::mem_row_major);
    }
    __syncthreads();

    __nv_bfloat16* dst = g_o + (size_t)win * 64 * 384 + head * 48;
    for (int li = tid; li < 64 * 48; li += 128) {
        int t = li / 48, d = li % 48;
        dst[(size_t)t * 384 + d] = __float2bfloat16(sS[t * 68 + d]);
    }
}

// ---------------- K8: depthwise 3x3 conv + bias + exact GELU (4 rows/block) ----------------
__global__ void __launch_bounds__(256) k_dwconv(const float* __restrict__ wgt,
                                                const float* __restrict__ bias) {
    __shared__ __nv_bfloat16 s[6 * 58 * 64];   // 6 input rows x 58 w x 64 chans
    int b = blockIdx.y, h0 = blockIdx.x * 4;   // grid (14, 32)
    int tid = threadIdx.x;
    int c = tid & 63, sub = tid >> 6;          // sub = 0..3: output row within group

    for (int cc = 0; cc < HID; cc += 64) {
        __syncthreads();
        for (int li = tid; li < 6 * 58 * 8; li += 256) {
            int hr = li / 464;          // 0..5 -> input row h0-1+hr
            int rem = li % 464;
            int wi = rem >> 3;          // 0..57
            int grp = (rem & 7) * 8;
            int hh = h0 - 1 + hr, ww = wi - 1;
            uint4 val = make_uint4(0u, 0u, 0u, 0u);
            if (hh >= 0 && hh < HH_ && ww >= 0 && ww < WW_)
                val = *(const uint4*)&g_m1[((size_t)b * NS + hh * WW_ + ww) * HID + cc + grp];
            *(uint4*)&s[(hr * 58 + wi) * 64 + grp] = val;
        }
        __syncthreads();

        int ch = cc + c;
        float w9[9];
#pragma unroll
        for (int i = 0; i < 9; i++) w9[i] = wgt[ch * 9 + i];
        float bv = bias[ch];
        int h = h0 + sub;
        for (int w0 = 0; w0 < WW_; w0++) {
            float acc = bv;
#pragma unroll
            for (int dy = 0; dy < 3; dy++)
#pragma unroll
                for (int dx = 0; dx < 3; dx++)
                    acc += __bfloat162float(s[((sub + dy) * 58 + w0 + dx) * 64 + c]) * w9[dy * 3 + dx];
            float gl = 0.5f * acc * (1.0f + erff(acc * 0.70710678118f));
            g_mg[((size_t)b * NS + h * WW_ + w0) * HID + ch] = __float2bfloat16(gl);
        }
    }
}

// ---------------- launch ----------------
extern "C" void kernel_launch(void* const* d_in, const int* in_sizes, int n_in,
                              void* d_out, int out_size) {
    (void)in_sizes; (void)n_in; (void)out_size;
    const float* x      = (const float*)d_in[0];
    const float* ln1_g  = (const float*)d_in[1];
    const float* ln1_b  = (const float*)d_in[2];
    const float* qkv_w  = (const float*)d_in[3];
    const float* proj_w = (const float*)d_in[4];
    const float* proj_b = (const float*)d_in[5];
    const float* ln2_g  = (const float*)d_in[6];
    const float* ln2_b  = (const float*)d_in[7];
    const float* fc1_w  = (const float*)d_in[8];
    const float* fc1_b  = (const float*)d_in[9];
    const float* dw_w   = (const float*)d_in[10];
    const float* dw_b   = (const float*)d_in[11];
    const float* fc2_w  = (const float*)d_in[12];
    const float* fc2_b  = (const float*)d_in[13];
    const float* gamma1 = (const float*)d_in[14];
    const float* gamma2 = (const float*)d_in[15];
    float* out = (float*)d_out;

    // idempotent, deterministic, capture-safe
    cudaFuncSetAttribute(k_gemm<0>, cudaFuncAttributeMaxDynamicSharedMemorySize, GEMM_DSMEM);
    cudaFuncSetAttribute(k_gemm<1>, cudaFuncAttributeMaxDynamicSharedMemorySize, GEMM_DSMEM);
    cudaFuncSetAttribute(k_gemm<2>, cudaFuncAttributeMaxDynamicSharedMemorySize, GEMM_DSMEM);
    cudaFuncSetAttribute(k_gemm<3>, cudaFuncAttributeMaxDynamicSharedMemorySize, GEMM_DSMEM);

    k_wprep_all<<<1728, 256>>>(qkv_w, proj_w, fc1_w, fc2_w);                       // launch 0
    k_transpose<<<dim3(NS / 32, CC_ / 32, BB), dim3(32, 8)>>>(x);                  // launch 1
    k_layernorm<0><<<MR, 128>>>(ln1_g, ln1_b);                                     // launch 2
    k_gemm<0><<<dim3(1152 / 128, MR / 128), 256, GEMM_DSMEM>>>(nullptr, nullptr, nullptr); // 3
    k_attn<<<dim3(NWIN, NHEADS), 128>>>();                                         // launch 4
    k_gemm<1><<<dim3(384 / 128, MR / 128), 256, GEMM_DSMEM>>>(proj_b, gamma1, nullptr);    // 5 <- ncu
    k_layernorm<1><<<MR, 128>>>(ln2_g, ln2_b);
    k_gemm<2><<<dim3(1536 / 128, MR / 128), 256, GEMM_DSMEM>>>(fc1_b, nullptr, nullptr);
    k_dwconv<<<dim3(14, BB), 256>>>(dw_w, dw_b);
    k_gemm<3><<<dim3(384 / 128, MR / 128), 256, GEMM_DSMEM>>>(fc2_b, gamma2, out);
}